// round 7
// baseline (speedup 1.0000x reference)
#include <cuda_runtime.h>
#include <cuda_fp16.h>
#include <cstdint>

#define B_   256
#define CIN  128
#define NPTS 1024
#define M_   1023
#define COUT 64
#define M3   3069
#define OUTW 1024
#define NTILES 1024          // m-tiles of 256 rows: 4 per batch
#define GRID_P 148

// ---------------- scratch (__device__ globals) ----------------------------
__device__ __half g_th[(size_t)B_ * NPTS * CIN];          // [b][n][c] fp16
__device__ __align__(256) unsigned char g_Wsw[3 * 2 * 16384]; // W image hi/lo
__device__ int g_idx_is64;

// ---------------- PTX helpers ---------------------------------------------
__device__ __forceinline__ uint32_t smem_u32(const void* p) {
    uint32_t a;
    asm("{ .reg .u64 t; cvta.to.shared.u64 t, %1; cvt.u32.u64 %0, t; }"
        : "=r"(a) : "l"(p));
    return a;
}
#define CP_ASYNC16(dst, src) \
    asm volatile("cp.async.cg.shared.global [%0], [%1], 16;" :: "r"(dst), "l"(src) : "memory")
#define CP_COMMIT() asm volatile("cp.async.commit_group;" ::: "memory")
#define CP_WAIT0()  asm volatile("cp.async.wait_group 0;" ::: "memory")

#define LDSM_X4(r0, r1, r2, r3, addr) \
    asm volatile("ldmatrix.sync.aligned.m8n8.x4.shared.b16 {%0,%1,%2,%3}, [%4];" \
        : "=r"(r0), "=r"(r1), "=r"(r2), "=r"(r3) : "r"(addr))

#define MMA_F16(d, a, b0, b1) \
    asm volatile("mma.sync.aligned.m16n8k16.row.col.f32.f16.f16.f32 " \
        "{%0,%1,%2,%3}, {%4,%5,%6,%7}, {%8,%9}, {%0,%1,%2,%3};" \
        : "+f"((d)[0]), "+f"((d)[1]), "+f"((d)[2]), "+f"((d)[3]) \
        : "r"((a)[0]), "r"((a)[1]), "r"((a)[2]), "r"((a)[3]), "r"(b0), "r"(b1))

// ---------------- kernel 0: index dtype detection --------------------------
__global__ void detect_kernel(const int* __restrict__ idx32) {
    __shared__ int any_nz;
    if (threadIdx.x == 0) any_nz = 0;
    __syncthreads();
    int nz = 0;
    for (int i = threadIdx.x; i < 1024; i += blockDim.x)
        nz |= (idx32[2 * i + 1] != 0);
    if (nz) atomicOr(&any_nz, 1);
    __syncthreads();
    if (threadIdx.x == 0) g_idx_is64 = any_nz ? 0 : 1;
}

// ---------------- kernel 1: transpose + fp16 convert -----------------------
__global__ void transpose_half_kernel(const float* __restrict__ trees) {
    __shared__ float tile[32][33];
    int b = blockIdx.z;
    int nBase = blockIdx.x * 32;
    int cBase = blockIdx.y * 32;
    int tx = threadIdx.x, ty = threadIdx.y;
    const float* src = trees + (size_t)b * CIN * NPTS;
    #pragma unroll
    for (int i = 0; i < 4; i++)
        tile[ty + 8 * i][tx] = src[(size_t)(cBase + ty + 8 * i) * NPTS + nBase + tx];
    __syncthreads();
    #pragma unroll
    for (int i = 0; i < 4; i++) {
        int n = nBase + ty + 8 * i;
        g_th[(size_t)(b * NPTS + n) * CIN + cBase + tx] =
            __float2half(tile[tx][ty + 8 * i]);
    }
}

// ---------------- kernel 2: W -> fp16 hi/lo swizzled image -----------------
// byte layout: tap*32768 + mat*16384 + o*256 + swz(g,o)*16 + (c&7)*2
__global__ void wprep_kernel(const float* __restrict__ W) {
    int i = blockIdx.x * 256 + threadIdx.x;
    if (i >= 3 * 64 * 128) return;
    int c = i & 127;
    int o = (i >> 7) & 63;
    int k = i >> 13;
    float v = W[(o * CIN + c) * 3 + k];
    __half h = __float2half(v);
    __half l = __float2half(v - __half2float(h));
    int g = c >> 3;
    uint32_t swz = (g & 8) | ((g & 7) ^ (o & 7));
    uint32_t off = k * 32768 + o * 256 + (swz << 4) + (c & 7) * 2;
    *(__half*)(g_Wsw + off)         = h;    // mat 0 (hi)
    *(__half*)(g_Wsw + off + 16384) = l;    // mat 1 (lo)
}

// ---------------- kernel 3: persistent gather + HMMA fp16 GEMM -------------
// grid 148, 512 threads (16 warps, 8m x 2n; warp tile 32m x 32o).
// Stage = 256 m-rows of one tap (64KB). 2-slot ring, prefetch one ahead.
// smem: W image 96KB | A ring 2 x 64KB
#define SM_W 0
#define SM_A 98304
#define SMEM_TOTAL 229376

__global__ void __launch_bounds__(512, 1) convtree_persist_kernel(
    const void* __restrict__ indexes_raw,
    const float* __restrict__ bias,
    float* __restrict__ out)
{
    extern __shared__ char smem[];
    const uint32_t sb = smem_u32(smem);
    const int tid  = threadIdx.x;
    const int lane = tid & 31;
    const int w    = tid >> 5;
    const int wm   = w & 7;        // m-group: rows wm*32 .. wm*32+31 (of 256)
    const int wn   = w >> 3;       // n-group: o wn*32 .. wn*32+31
    const int cta  = blockIdx.x;
    const int is64 = g_idx_is64;
    const int* i32 = (const int*)indexes_raw;
    const long long* i64 = (const long long*)indexes_raw;

    // ---- W image, loaded once per CTA (pre-swizzled, linear copy) ----
    for (int i = tid; i < 6144; i += 512)
        CP_ASYNC16(sb + SM_W + i * 16, (const char*)g_Wsw + i * 16);
    CP_COMMIT();

    // ---- per-thread bias values ----
    const int ocl = (lane & 3) * 2;
    float bv[2][2][2];
    #pragma unroll
    for (int ntp = 0; ntp < 2; ntp++)
        #pragma unroll
        for (int sub = 0; sub < 2; sub++) {
            int o = wn * 32 + ntp * 16 + sub * 8 + ocl;
            bv[ntp][sub][0] = bias[o];
            bv[ntp][sub][1] = bias[o + 1];
        }

    const int K = (NTILES - cta + GRID_P - 1) / GRID_P;  // tiles for this CTA
    const int S = 3 * K;                                  // stages (tile, tap)

    // stage loader: stage s = (local tile s/3, tap s%3) into ring slot s&1
    // 512 threads: 2 threads per m-row, 8 x 16B each
    auto load_stage = [&](int s) {
        int j = s / 3, tap = s - 3 * j;
        int tile = cta + j * GRID_P;
        int b = tile >> 2, m0 = (tile & 3) << 8;
        int row = tid >> 1, half = tid & 1;
        int gm = m0 + row;
        int n = 0;
        if (gm < M_) {
            int flat = b * M3 + 3 * gm + tap;
            n = (is64 ? (int)i64[flat] : i32[flat]) & (NPTS - 1);
        }
        const char* src = (const char*)(g_th + ((size_t)(b * NPTS + n) << 7))
                          + half * 128;
        uint32_t dbase = sb + SM_A + ((s & 1) << 16) + row * 256;
        #pragma unroll
        for (int q = 0; q < 8; q++) {
            int g = half * 8 + q;
            uint32_t swz = (g & 8) | ((g & 7) ^ (row & 7));
            CP_ASYNC16(dbase + (swz << 4), src + q * 16);
        }
        CP_COMMIT();
    };

    load_stage(0);

    float acc[2][2][2][4];   // [mt][ntp][sub][quad]
    #pragma unroll
    for (int a = 0; a < 2; a++)
        #pragma unroll
        for (int b2 = 0; b2 < 2; b2++)
            #pragma unroll
            for (int c = 0; c < 2; c++)
                #pragma unroll
                for (int d = 0; d < 4; d++) acc[a][b2][c][d] = 0.0f;

    const int ag = lane >> 4;
    const int bg = (lane >> 3) & 1;
    const int brow_base = wn * 32 + ((lane >> 4) << 3) + (lane & 7);
    const int l7 = lane & 7;

    for (int s = 0; s < S; s++) {
        CP_WAIT0();            // stage s (and W on first iter) arrived
        __syncthreads();       // all warps done with slot (s+1)&1's old data

        if (s + 1 < S) load_stage(s + 1);   // prefetch into freed slot

        const int tap = s - 3 * (s / 3);
        const uint32_t abase = sb + SM_A + ((s & 1) << 16)
                             + (wm * 32 + (lane & 15)) * 256;
        const uint32_t wtap = sb + SM_W + tap * 32768;

        #pragma unroll
        for (int ks = 0; ks < 8; ks++) {
            const int g0 = ks * 2;
            uint32_t ah0[4], ah1[4];
            {
                int ga = g0 + ag;
                uint32_t swA = (uint32_t)((ga & 8) | ((ga & 7) ^ l7));
                LDSM_X4(ah0[0], ah0[1], ah0[2], ah0[3], abase + (swA << 4));
                LDSM_X4(ah1[0], ah1[1], ah1[2], ah1[3], abase + 4096 + (swA << 4));
            }
            int gb = g0 + bg;
            uint32_t swB = (uint32_t)((gb & 8) | ((gb & 7) ^ l7));
            #pragma unroll
            for (int mat = 0; mat < 2; mat++) {
                #pragma unroll
                for (int ntp = 0; ntp < 2; ntp++) {
                    uint32_t waddr = wtap + mat * 16384
                                   + (brow_base + ntp * 16) * 256 + (swB << 4);
                    uint32_t bh[4];
                    LDSM_X4(bh[0], bh[1], bh[2], bh[3], waddr);
                    MMA_F16(acc[0][ntp][0], ah0, bh[0], bh[1]);
                    MMA_F16(acc[0][ntp][1], ah0, bh[2], bh[3]);
                    MMA_F16(acc[1][ntp][0], ah1, bh[0], bh[1]);
                    MMA_F16(acc[1][ntp][1], ah1, bh[2], bh[3]);
                }
            }
        }

        // ---- epilogue after the 3rd tap of a tile: direct coalesced stores ----
        if (tap == 2) {
            int tile = cta + (s / 3) * GRID_P;
            int b = tile >> 2, m0 = (tile & 3) << 8;
            float* ob = out + (((size_t)b * COUT) << 10);
            int rl = lane >> 2;
            #pragma unroll
            for (int mt = 0; mt < 2; mt++) {
                int gmb = m0 + wm * 32 + mt * 16 + rl;
                #pragma unroll
                for (int ntp = 0; ntp < 2; ntp++) {
                    #pragma unroll
                    for (int sub = 0; sub < 2; sub++) {
                        int o = wn * 32 + ntp * 16 + sub * 8 + ocl;
                        float* p0 = ob + (((size_t)o) << 10) + 1;
                        float* p1 = ob + (((size_t)(o + 1)) << 10) + 1;
                        float* q = &acc[mt][ntp][sub][0];
                        if (gmb < M_) {
                            p0[gmb] = q[0] + bv[ntp][sub][0];
                            p1[gmb] = q[1] + bv[ntp][sub][1];
                        }
                        if (gmb + 8 < M_) {
                            p0[gmb + 8] = q[2] + bv[ntp][sub][0];
                            p1[gmb + 8] = q[3] + bv[ntp][sub][1];
                        }
                        q[0] = q[1] = q[2] = q[3] = 0.0f;
                    }
                }
            }
        }
    }
}

// ---------------- kernel 4: zero column + optional index tail --------------
__global__ void tail_kernel(const void* __restrict__ idx_raw,
                            float* __restrict__ out, int mode) {
    int i = blockIdx.x * 256 + threadIdx.x;
    const int is64 = g_idx_is64;
    const int* i32 = (const int*)idx_raw;
    const long long* i64 = (const long long*)idx_raw;
    if (i < B_ * COUT) out[(size_t)i * OUTW] = 0.0f;
    if (i < B_ * M3) {
        long long v = is64 ? i64[i] : (long long)i32[i];
        if (mode == 1) {
            out[(size_t)B_ * COUT * OUTW + i] = (float)v;
        } else if (mode == 2) {
            ((long long*)out)[(size_t)(B_ * COUT * OUTW) / 2 + i] = v;
        }
    }
}

// ---------------------------------------------------------------------------
extern "C" void kernel_launch(void* const* d_in, const int* in_sizes, int n_in,
                              void* d_out, int out_size) {
    const float* trees = nullptr;
    const void* indexes = nullptr;
    const float* W = nullptr;
    const float* bias = nullptr;
    for (int i = 0; i < n_in; i++) {
        switch (in_sizes[i]) {
            case B_ * CIN * NPTS: trees   = (const float*)d_in[i]; break;
            case B_ * M3:         indexes = d_in[i];               break;
            case COUT * CIN * 3:  W       = (const float*)d_in[i]; break;
            case COUT:            bias    = (const float*)d_in[i]; break;
        }
    }
    float* out = (float*)d_out;

    cudaFuncSetAttribute(convtree_persist_kernel,
                         cudaFuncAttributeMaxDynamicSharedMemorySize, SMEM_TOTAL);

    detect_kernel<<<1, 256>>>((const int*)indexes);
    transpose_half_kernel<<<dim3(NPTS / 32, CIN / 32, B_), dim3(32, 8)>>>(trees);
    wprep_kernel<<<(3 * 64 * 128 + 255) / 256, 256>>>(W);
    convtree_persist_kernel<<<GRID_P, 512, SMEM_TOTAL>>>(indexes, bias, out);

    long long R = (long long)B_ * COUT * OUTW;
    long long I = (long long)B_ * M3;
    int mode = 0;
    if ((long long)out_size >= R + 2 * I)      mode = 2;
    else if ((long long)out_size >= R + I)     mode = 1;
    tail_kernel<<<(B_ * M3 + 255) / 256, 256>>>(indexes, out, mode);
}

// round 9
// speedup vs baseline: 1.1370x; 1.1370x over previous
#include <cuda_runtime.h>
#include <cuda_fp16.h>
#include <cstdint>

#define B_   256
#define CIN  128
#define NPTS 1024
#define M_   1023
#define COUT 64
#define M3   3069
#define OUTW 1024
#define NTILES 2048          // m-tiles of 128 rows: 8 per batch
#define GRID_P 148
#define NSLOT 5

// ---------------- scratch (__device__ globals) ----------------------------
__device__ __half g_th[(size_t)B_ * NPTS * CIN];       // [b][n][c] fp16
__device__ __align__(256) unsigned char g_Wsw[3 * 16384]; // W fp16 image
__device__ int g_idx_is64;

// ---------------- PTX helpers ---------------------------------------------
__device__ __forceinline__ uint32_t smem_u32(const void* p) {
    uint32_t a;
    asm("{ .reg .u64 t; cvta.to.shared.u64 t, %1; cvt.u32.u64 %0, t; }"
        : "=r"(a) : "l"(p));
    return a;
}
#define CP_ASYNC16(dst, src) \
    asm volatile("cp.async.cg.shared.global [%0], [%1], 16;" :: "r"(dst), "l"(src) : "memory")
#define CP_COMMIT() asm volatile("cp.async.commit_group;" ::: "memory")
#define CP_WAIT0()  asm volatile("cp.async.wait_group 0;" ::: "memory")
#define CP_WAIT1()  asm volatile("cp.async.wait_group 1;" ::: "memory")
#define CP_WAIT2()  asm volatile("cp.async.wait_group 2;" ::: "memory")
#define CP_WAIT3()  asm volatile("cp.async.wait_group 3;" ::: "memory")

#define LDSM_X4(r0, r1, r2, r3, addr) \
    asm volatile("ldmatrix.sync.aligned.m8n8.x4.shared.b16 {%0,%1,%2,%3}, [%4];" \
        : "=r"(r0), "=r"(r1), "=r"(r2), "=r"(r3) : "r"(addr))

#define MMA_F16(d, a, b0, b1) \
    asm volatile("mma.sync.aligned.m16n8k16.row.col.f32.f16.f16.f32 " \
        "{%0,%1,%2,%3}, {%4,%5,%6,%7}, {%8,%9}, {%0,%1,%2,%3};" \
        : "+f"((d)[0]), "+f"((d)[1]), "+f"((d)[2]), "+f"((d)[3]) \
        : "r"((a)[0]), "r"((a)[1]), "r"((a)[2]), "r"((a)[3]), "r"(b0), "r"(b1))

// ---------------- kernel 0: index dtype detection --------------------------
__global__ void detect_kernel(const int* __restrict__ idx32) {
    __shared__ int any_nz;
    if (threadIdx.x == 0) any_nz = 0;
    __syncthreads();
    int nz = 0;
    for (int i = threadIdx.x; i < 1024; i += blockDim.x)
        nz |= (idx32[2 * i + 1] != 0);
    if (nz) atomicOr(&any_nz, 1);
    __syncthreads();
    if (threadIdx.x == 0) g_idx_is64 = any_nz ? 0 : 1;
}

// ---------------- kernel 1: transpose + fp16 convert -----------------------
__global__ void transpose_half_kernel(const float* __restrict__ trees) {
    __shared__ float tile[32][33];
    int b = blockIdx.z;
    int nBase = blockIdx.x * 32;
    int cBase = blockIdx.y * 32;
    int tx = threadIdx.x, ty = threadIdx.y;
    const float* src = trees + (size_t)b * CIN * NPTS;
    #pragma unroll
    for (int i = 0; i < 4; i++)
        tile[ty + 8 * i][tx] = src[(size_t)(cBase + ty + 8 * i) * NPTS + nBase + tx];
    __syncthreads();
    #pragma unroll
    for (int i = 0; i < 4; i++) {
        int n = nBase + ty + 8 * i;
        g_th[(size_t)(b * NPTS + n) * CIN + cBase + tx] =
            __float2half(tile[tx][ty + 8 * i]);
    }
}

// ---------------- kernel 2: W -> fp16 swizzled image -----------------------
// byte layout: tap*16384 + o*256 + swz(g,o)*16 + (c&7)*2
__global__ void wprep_kernel(const float* __restrict__ W) {
    int i = blockIdx.x * 256 + threadIdx.x;
    if (i >= 3 * 64 * 128) return;
    int c = i & 127;
    int o = (i >> 7) & 63;
    int k = i >> 13;
    float v = W[(o * CIN + c) * 3 + k];
    int g = c >> 3;
    uint32_t swz = (g & 8) | ((g & 7) ^ (o & 7));
    uint32_t off = k * 16384 + o * 256 + (swz << 4) + (c & 7) * 2;
    *(__half*)(g_Wsw + off) = __float2half(v);
}

// ---------------- kernel 3: persistent gather + HMMA fp16 GEMM -------------
// grid 148, 512 threads: 16 warps = 2 k-groups x (4m x 2n), warp tile 32m x 32o.
// Stage = 128 m-rows of one tap (32KB). 5-slot ring, prefetch distance 4.
// k-group kg handles c in [kg*64, kg*64+64); partials reduced per tile via smem.
#define SM_W 0
#define SM_A 49152
#define SMEM_TOTAL 212992

__global__ void __launch_bounds__(512, 1) convtree_persist_kernel(
    const void* __restrict__ indexes_raw,
    const float* __restrict__ bias,
    float* __restrict__ out)
{
    extern __shared__ char smem[];
    const uint32_t sb = smem_u32(smem);
    const int tid  = threadIdx.x;
    const int lane = tid & 31;
    const int w    = tid >> 5;
    const int kg   = w >> 3;          // k-group 0/1
    const int wm   = w & 3;           // m-group: rows wm*32 .. wm*32+31
    const int wn   = (w >> 2) & 1;    // n-group: o wn*32 .. wn*32+31
    const int cta  = blockIdx.x;
    const int is64 = g_idx_is64;
    const int* i32 = (const int*)indexes_raw;
    const long long* i64 = (const long long*)indexes_raw;

    // ---- W image, loaded once per CTA (pre-swizzled, linear copy) ----
    for (int i = tid; i < 3072; i += 512)
        CP_ASYNC16(sb + SM_W + i * 16, (const char*)g_Wsw + i * 16);
    CP_COMMIT();

    // ---- per-thread bias values (used by k-group 0 in epilogue) ----
    const int ocl = (lane & 3) * 2;
    float bv[2][2][2];
    #pragma unroll
    for (int ntp = 0; ntp < 2; ntp++)
        #pragma unroll
        for (int sub = 0; sub < 2; sub++) {
            int o = wn * 32 + ntp * 16 + sub * 8 + ocl;
            bv[ntp][sub][0] = bias[o];
            bv[ntp][sub][1] = bias[o + 1];
        }

    const int K = (NTILES - cta + GRID_P - 1) / GRID_P;
    const int S = 3 * K;

    // stage loader: stage s = (local tile s/3, tap s%3) into slot s%NSLOT
    auto load_stage = [&](int s) {
        int j = s / 3, tap = s - 3 * j;
        int tile = cta + j * GRID_P;
        int b = tile >> 3, m0 = (tile & 7) << 7;
        int row = tid >> 2, quarter = tid & 3;
        int gm = m0 + row;
        int n = 0;
        if (gm < M_) {
            int flat = b * M3 + 3 * gm + tap;
            n = (is64 ? (int)i64[flat] : i32[flat]) & (NPTS - 1);
        }
        const char* src = (const char*)(g_th + ((size_t)(b * NPTS + n) << 7))
                          + quarter * 64;
        uint32_t dbase = sb + SM_A + (s % NSLOT) * 32768 + row * 256;
        #pragma unroll
        for (int q = 0; q < 4; q++) {
            int g = quarter * 4 + q;
            uint32_t swz = (g & 8) | ((g & 7) ^ (row & 7));
            CP_ASYNC16(dbase + (swz << 4), src + q * 16);
        }
        CP_COMMIT();
    };

    load_stage(0);
    load_stage(1);
    load_stage(2);
    load_stage(3);

    float acc[2][2][2][4];   // [mt][ntp][sub][quad]
    #pragma unroll
    for (int a = 0; a < 2; a++)
        #pragma unroll
        for (int b2 = 0; b2 < 2; b2++)
            #pragma unroll
            for (int c = 0; c < 2; c++)
                #pragma unroll
                for (int d = 0; d < 4; d++) acc[a][b2][c][d] = 0.0f;

    const int ag = lane >> 4;
    const int bg = (lane >> 3) & 1;
    const int brow_base = wn * 32 + ((lane >> 4) << 3) + (lane & 7);
    const int l7 = lane & 7;
    const int rl = lane >> 2;

    for (int s = 0; s < S; s++) {
        int rem = S - 1 - s;
        if (rem >= 3) CP_WAIT3();
        else if (rem == 2) CP_WAIT2();
        else if (rem == 1) CP_WAIT1();
        else CP_WAIT0();
        __syncthreads();                     // stage s visible

        if (s + 4 < S) load_stage(s + 4);

        const int tap = s - 3 * (s / 3);
        const uint32_t abase = sb + SM_A + (s % NSLOT) * 32768
                             + (wm * 32 + (lane & 15)) * 256;
        const uint32_t wtap = sb + SM_W + tap * 16384;

        #pragma unroll
        for (int ks = 0; ks < 4; ks++) {
            const int g0 = kg * 8 + ks * 2;
            uint32_t ah0[4], ah1[4];
            {
                int ga = g0 + ag;
                uint32_t swA = (uint32_t)((ga & 8) | ((ga & 7) ^ l7));
                LDSM_X4(ah0[0], ah0[1], ah0[2], ah0[3], abase + (swA << 4));
                LDSM_X4(ah1[0], ah1[1], ah1[2], ah1[3], abase + 4096 + (swA << 4));
            }
            int gb = g0 + bg;
            uint32_t swB = (uint32_t)((gb & 8) | ((gb & 7) ^ l7));
            #pragma unroll
            for (int ntp = 0; ntp < 2; ntp++) {
                uint32_t bh[4];
                LDSM_X4(bh[0], bh[1], bh[2], bh[3],
                        wtap + (brow_base + ntp * 16) * 256 + (swB << 4));
                MMA_F16(acc[0][ntp][0], ah0, bh[0], bh[1]);
                MMA_F16(acc[0][ntp][1], ah0, bh[2], bh[3]);
                MMA_F16(acc[1][ntp][0], ah1, bh[0], bh[1]);
                MMA_F16(acc[1][ntp][1], ah1, bh[2], bh[3]);
            }
        }

        // ---- after tap 2: reduce k-groups via freed slot, then store ----
        if (tap == 2) {
            float* stag = (float*)(smem + SM_A + (s % NSLOT) * 32768); // [o][m] 64x128
            __syncthreads();   // ALL warps done reading slot s%NSLOT (LDSM) before reuse
            if (kg == 1) {
                #pragma unroll
                for (int mt = 0; mt < 2; mt++) {
                    int m = wm * 32 + mt * 16 + rl;
                    #pragma unroll
                    for (int ntp = 0; ntp < 2; ntp++)
                        #pragma unroll
                        for (int sub = 0; sub < 2; sub++) {
                            int o = wn * 32 + ntp * 16 + sub * 8 + ocl;
                            float* q = &acc[mt][ntp][sub][0];
                            stag[o * 128 + m]           = q[0];
                            stag[(o + 1) * 128 + m]     = q[1];
                            stag[o * 128 + m + 8]       = q[2];
                            stag[(o + 1) * 128 + m + 8] = q[3];
                            q[0] = q[1] = q[2] = q[3] = 0.0f;
                        }
                }
            }
            __syncthreads();   // kg1 partials visible to kg0
            if (kg == 0) {
                int tile = cta + (s / 3) * GRID_P;
                int b = tile >> 3, m0 = (tile & 7) << 7;
                float* ob = out + (((size_t)b * COUT) << 10);
                #pragma unroll
                for (int mt = 0; mt < 2; mt++) {
                    int m = wm * 32 + mt * 16 + rl;
                    int gmb = m0 + m;
                    #pragma unroll
                    for (int ntp = 0; ntp < 2; ntp++)
                        #pragma unroll
                        for (int sub = 0; sub < 2; sub++) {
                            int o = wn * 32 + ntp * 16 + sub * 8 + ocl;
                            float* p0 = ob + (((size_t)o) << 10) + 1;
                            float* p1 = ob + (((size_t)(o + 1)) << 10) + 1;
                            float* q = &acc[mt][ntp][sub][0];
                            float v0 = q[0] + stag[o * 128 + m]           + bv[ntp][sub][0];
                            float v1 = q[1] + stag[(o + 1) * 128 + m]     + bv[ntp][sub][1];
                            float v2 = q[2] + stag[o * 128 + m + 8]       + bv[ntp][sub][0];
                            float v3 = q[3] + stag[(o + 1) * 128 + m + 8] + bv[ntp][sub][1];
                            if (gmb < M_) { p0[gmb] = v0; p1[gmb] = v1; }
                            if (gmb + 8 < M_) { p0[gmb + 8] = v2; p1[gmb + 8] = v3; }
                            q[0] = q[1] = q[2] = q[3] = 0.0f;
                        }
                }
            }
        }
    }
}

// ---------------- kernel 4: zero column + optional index tail --------------
__global__ void tail_kernel(const void* __restrict__ idx_raw,
                            float* __restrict__ out, int mode) {
    int i = blockIdx.x * 256 + threadIdx.x;
    const int is64 = g_idx_is64;
    const int* i32 = (const int*)idx_raw;
    const long long* i64 = (const long long*)idx_raw;
    if (i < B_ * COUT) out[(size_t)i * OUTW] = 0.0f;
    if (i < B_ * M3) {
        long long v = is64 ? i64[i] : (long long)i32[i];
        if (mode == 1) {
            out[(size_t)B_ * COUT * OUTW + i] = (float)v;
        } else if (mode == 2) {
            ((long long*)out)[(size_t)(B_ * COUT * OUTW) / 2 + i] = v;
        }
    }
}

// ---------------------------------------------------------------------------
extern "C" void kernel_launch(void* const* d_in, const int* in_sizes, int n_in,
                              void* d_out, int out_size) {
    const float* trees = nullptr;
    const void* indexes = nullptr;
    const float* W = nullptr;
    const float* bias = nullptr;
    for (int i = 0; i < n_in; i++) {
        switch (in_sizes[i]) {
            case B_ * CIN * NPTS: trees   = (const float*)d_in[i]; break;
            case B_ * M3:         indexes = d_in[i];               break;
            case COUT * CIN * 3:  W       = (const float*)d_in[i]; break;
            case COUT:            bias    = (const float*)d_in[i]; break;
        }
    }
    float* out = (float*)d_out;

    cudaFuncSetAttribute(convtree_persist_kernel,
                         cudaFuncAttributeMaxDynamicSharedMemorySize, SMEM_TOTAL);

    detect_kernel<<<1, 256>>>((const int*)indexes);
    transpose_half_kernel<<<dim3(NPTS / 32, CIN / 32, B_), dim3(32, 8)>>>(trees);
    wprep_kernel<<<(3 * 64 * 128 + 255) / 256, 256>>>(W);
    convtree_persist_kernel<<<GRID_P, 512, SMEM_TOTAL>>>(indexes, bias, out);

    long long R = (long long)B_ * COUT * OUTW;
    long long I = (long long)B_ * M3;
    int mode = 0;
    if ((long long)out_size >= R + 2 * I)      mode = 2;
    else if ((long long)out_size >= R + I)     mode = 1;
    tail_kernel<<<(B_ * M3 + 255) / 256, 256>>>(indexes, out, mode);
}

// round 10
// speedup vs baseline: 1.1860x; 1.0431x over previous
#include <cuda_runtime.h>
#include <cuda_fp16.h>
#include <cstdint>

#define B_   256
#define CIN  128
#define NPTS 1024
#define M_   1023
#define COUT 64
#define M3   3069
#define OUTW 1024
#define NTILES 2048          // m-tiles of 128 rows: 8 per batch
#define GRID_P 148
#define NSLOT 5
#define KMAX  14             // ceil(2048/148)

// ---------------- scratch (__device__ globals) ----------------------------
__device__ __half g_th[(size_t)B_ * NPTS * CIN];       // [b][n][c] fp16
__device__ __align__(256) unsigned char g_Wsw[3 * 16384]; // W fp16 image
__device__ int g_idx_is64;

// ---------------- PTX helpers ---------------------------------------------
__device__ __forceinline__ uint32_t smem_u32(const void* p) {
    uint32_t a;
    asm("{ .reg .u64 t; cvta.to.shared.u64 t, %1; cvt.u32.u64 %0, t; }"
        : "=r"(a) : "l"(p));
    return a;
}
#define CP_ASYNC16(dst, src) \
    asm volatile("cp.async.cg.shared.global [%0], [%1], 16;" :: "r"(dst), "l"(src) : "memory")
#define CP_COMMIT() asm volatile("cp.async.commit_group;" ::: "memory")
#define CP_WAIT0()  asm volatile("cp.async.wait_group 0;" ::: "memory")
#define CP_WAIT1()  asm volatile("cp.async.wait_group 1;" ::: "memory")
#define CP_WAIT2()  asm volatile("cp.async.wait_group 2;" ::: "memory")
#define CP_WAIT3()  asm volatile("cp.async.wait_group 3;" ::: "memory")

#define LDSM_X4(r0, r1, r2, r3, addr) \
    asm volatile("ldmatrix.sync.aligned.m8n8.x4.shared.b16 {%0,%1,%2,%3}, [%4];" \
        : "=r"(r0), "=r"(r1), "=r"(r2), "=r"(r3) : "r"(addr))

#define MMA_F16(d, a, b0, b1) \
    asm volatile("mma.sync.aligned.m16n8k16.row.col.f32.f16.f16.f32 " \
        "{%0,%1,%2,%3}, {%4,%5,%6,%7}, {%8,%9}, {%0,%1,%2,%3};" \
        : "+f"((d)[0]), "+f"((d)[1]), "+f"((d)[2]), "+f"((d)[3]) \
        : "r"((a)[0]), "r"((a)[1]), "r"((a)[2]), "r"((a)[3]), "r"(b0), "r"(b1))

// ---------------- kernel 0: index dtype detection --------------------------
__global__ void detect_kernel(const int* __restrict__ idx32) {
    __shared__ int any_nz;
    if (threadIdx.x == 0) any_nz = 0;
    __syncthreads();
    int nz = 0;
    for (int i = threadIdx.x; i < 1024; i += blockDim.x)
        nz |= (idx32[2 * i + 1] != 0);
    if (nz) atomicOr(&any_nz, 1);
    __syncthreads();
    if (threadIdx.x == 0) g_idx_is64 = any_nz ? 0 : 1;
}

// ---------------- kernel 1: transpose + fp16 convert -----------------------
__global__ void transpose_half_kernel(const float* __restrict__ trees) {
    __shared__ float tile[32][33];
    int b = blockIdx.z;
    int nBase = blockIdx.x * 32;
    int cBase = blockIdx.y * 32;
    int tx = threadIdx.x, ty = threadIdx.y;
    const float* src = trees + (size_t)b * CIN * NPTS;
    #pragma unroll
    for (int i = 0; i < 4; i++)
        tile[ty + 8 * i][tx] = src[(size_t)(cBase + ty + 8 * i) * NPTS + nBase + tx];
    __syncthreads();
    #pragma unroll
    for (int i = 0; i < 4; i++) {
        int n = nBase + ty + 8 * i;
        g_th[(size_t)(b * NPTS + n) * CIN + cBase + tx] =
            __float2half(tile[tx][ty + 8 * i]);
    }
}

// ---------------- kernel 2: W -> fp16 swizzled image -----------------------
// byte layout: tap*16384 + o*256 + swz(g,o)*16 + (c&7)*2
__global__ void wprep_kernel(const float* __restrict__ W) {
    int i = blockIdx.x * 256 + threadIdx.x;
    if (i >= 3 * 64 * 128) return;
    int c = i & 127;
    int o = (i >> 7) & 63;
    int k = i >> 13;
    float v = W[(o * CIN + c) * 3 + k];
    int g = c >> 3;
    uint32_t swz = (g & 8) | ((g & 7) ^ (o & 7));
    uint32_t off = k * 16384 + o * 256 + (swz << 4) + (c & 7) * 2;
    *(__half*)(g_Wsw + off) = __float2half(v);
}

// ---------------- kernel 3: persistent gather + HMMA fp16 GEMM -------------
// grid 148, 512 threads: 16 warps = 2 k-groups x (4m x 2n), warp tile 32m x 32o.
// Stage = 128 m-rows of one tap (32KB). 5-slot ring, prefetch distance 4.
// All gather indices preloaded to smem (uint16) once per CTA.
#define SM_W   0
#define SM_IDX 49152
#define SM_A   61440
#define SMEM_TOTAL (61440 + NSLOT * 32768)   // 225280

__global__ void __launch_bounds__(512, 1) convtree_persist_kernel(
    const void* __restrict__ indexes_raw,
    const float* __restrict__ bias,
    float* __restrict__ out)
{
    extern __shared__ char smem[];
    const uint32_t sb = smem_u32(smem);
    const int tid  = threadIdx.x;
    const int lane = tid & 31;
    const int w    = tid >> 5;
    const int kg   = w >> 3;          // k-group 0/1
    const int wm   = w & 3;           // m-group: rows wm*32 .. wm*32+31
    const int wn   = (w >> 2) & 1;    // n-group: o wn*32 .. wn*32+31
    const int cta  = blockIdx.x;
    const int is64 = g_idx_is64;
    const int* i32 = (const int*)indexes_raw;
    const long long* i64 = (const long long*)indexes_raw;
    uint16_t* sidx = (uint16_t*)(smem + SM_IDX);

    const int K = (NTILES - cta + GRID_P - 1) / GRID_P;
    const int S = 3 * K;

    // ---- W image, loaded once per CTA (pre-swizzled, linear copy) ----
    for (int i = tid; i < 3072; i += 512)
        CP_ASYNC16(sb + SM_W + i * 16, (const char*)g_Wsw + i * 16);
    CP_COMMIT();

    // ---- preload ALL gather indices for this CTA's tiles (uint16) ----
    for (int e = tid; e < K * 384; e += 512) {
        int j = e / 384, i2 = e - j * 384;
        int tile = cta + j * GRID_P;
        int b = tile >> 3, m0 = (tile & 7) << 7;
        int gm = m0 + i2 / 3;
        int v = 0;
        if (gm < M_) {
            int flat = b * M3 + 3 * gm + (i2 % 3);
            v = is64 ? (int)i64[flat] : i32[flat];
        }
        sidx[e] = (uint16_t)(v & (NPTS - 1));
    }

    // ---- per-thread bias values (used by k-group 0 in epilogue) ----
    const int ocl = (lane & 3) * 2;
    float bv[2][2][2];
    #pragma unroll
    for (int ntp = 0; ntp < 2; ntp++)
        #pragma unroll
        for (int sub = 0; sub < 2; sub++) {
            int o = wn * 32 + ntp * 16 + sub * 8 + ocl;
            bv[ntp][sub][0] = bias[o];
            bv[ntp][sub][1] = bias[o + 1];
        }
    __syncthreads();   // sidx visible

    // stage loader: stage s = (local tile s/3, tap s%3) into slot s%NSLOT
    auto load_stage = [&](int s) {
        int j = s / 3, tap = s - 3 * j;
        int tile = cta + j * GRID_P;
        int b = tile >> 3;
        int row = tid >> 2, quarter = tid & 3;
        int n = sidx[j * 384 + row * 3 + tap];
        const char* src = (const char*)(g_th + ((size_t)(b * NPTS + n) << 7))
                          + quarter * 64;
        uint32_t dbase = sb + SM_A + (s % NSLOT) * 32768 + row * 256;
        #pragma unroll
        for (int q = 0; q < 4; q++) {
            int g = quarter * 4 + q;
            uint32_t swz = (g & 8) | ((g & 7) ^ (row & 7));
            CP_ASYNC16(dbase + (swz << 4), src + q * 16);
        }
        CP_COMMIT();
    };

    load_stage(0);
    load_stage(1);
    load_stage(2);
    load_stage(3);

    float acc[2][2][2][4];   // [mt][ntp][sub][quad]
    #pragma unroll
    for (int a = 0; a < 2; a++)
        #pragma unroll
        for (int b2 = 0; b2 < 2; b2++)
            #pragma unroll
            for (int c = 0; c < 2; c++)
                #pragma unroll
                for (int d = 0; d < 4; d++) acc[a][b2][c][d] = 0.0f;

    const int ag = lane >> 4;
    const int bg = (lane >> 3) & 1;
    const int brow_base = wn * 32 + ((lane >> 4) << 3) + (lane & 7);
    const int l7 = lane & 7;
    const int rl = lane >> 2;

    for (int s = 0; s < S; s++) {
        int rem = S - 1 - s;
        if (rem >= 3) CP_WAIT3();
        else if (rem == 2) CP_WAIT2();
        else if (rem == 1) CP_WAIT1();
        else CP_WAIT0();
        __syncthreads();                     // stage s visible

        if (s + 4 < S) load_stage(s + 4);

        const int tap = s - 3 * (s / 3);
        const uint32_t abase = sb + SM_A + (s % NSLOT) * 32768
                             + (wm * 32 + (lane & 15)) * 256;
        const uint32_t wtap = sb + SM_W + tap * 16384;

        // process k-steps in pairs: burst 8 independent LDSM, then 16 MMA
        #pragma unroll
        for (int kp = 0; kp < 2; kp++) {
            uint32_t af[2][2][4];   // [ks][mt]
            uint32_t bf[2][2][4];   // [ks][ntp]
            #pragma unroll
            for (int ks = 0; ks < 2; ks++) {
                const int g0 = kg * 8 + (kp * 2 + ks) * 2;
                int ga = g0 + ag;
                uint32_t swA = (uint32_t)((ga & 8) | ((ga & 7) ^ l7));
                LDSM_X4(af[ks][0][0], af[ks][0][1], af[ks][0][2], af[ks][0][3],
                        abase + (swA << 4));
                LDSM_X4(af[ks][1][0], af[ks][1][1], af[ks][1][2], af[ks][1][3],
                        abase + 4096 + (swA << 4));
                int gb = g0 + bg;
                uint32_t swB = (uint32_t)((gb & 8) | ((gb & 7) ^ l7));
                LDSM_X4(bf[ks][0][0], bf[ks][0][1], bf[ks][0][2], bf[ks][0][3],
                        wtap + brow_base * 256 + (swB << 4));
                LDSM_X4(bf[ks][1][0], bf[ks][1][1], bf[ks][1][2], bf[ks][1][3],
                        wtap + (brow_base + 16) * 256 + (swB << 4));
            }
            #pragma unroll
            for (int ks = 0; ks < 2; ks++) {
                #pragma unroll
                for (int ntp = 0; ntp < 2; ntp++) {
                    MMA_F16(acc[0][ntp][0], af[ks][0], bf[ks][ntp][0], bf[ks][ntp][1]);
                    MMA_F16(acc[0][ntp][1], af[ks][0], bf[ks][ntp][2], bf[ks][ntp][3]);
                    MMA_F16(acc[1][ntp][0], af[ks][1], bf[ks][ntp][0], bf[ks][ntp][1]);
                    MMA_F16(acc[1][ntp][1], af[ks][1], bf[ks][ntp][2], bf[ks][ntp][3]);
                }
            }
        }

        // ---- after tap 2: reduce k-groups via freed slot, then store ----
        if (tap == 2) {
            float* stag = (float*)(smem + SM_A + (s % NSLOT) * 32768); // [o][m] 64x128
            __syncthreads();   // ALL warps done reading slot s%NSLOT before reuse
            if (kg == 1) {
                #pragma unroll
                for (int mt = 0; mt < 2; mt++) {
                    int m = wm * 32 + mt * 16 + rl;
                    #pragma unroll
                    for (int ntp = 0; ntp < 2; ntp++)
                        #pragma unroll
                        for (int sub = 0; sub < 2; sub++) {
                            int o = wn * 32 + ntp * 16 + sub * 8 + ocl;
                            float* q = &acc[mt][ntp][sub][0];
                            stag[o * 128 + m]           = q[0];
                            stag[(o + 1) * 128 + m]     = q[1];
                            stag[o * 128 + m + 8]       = q[2];
                            stag[(o + 1) * 128 + m + 8] = q[3];
                            q[0] = q[1] = q[2] = q[3] = 0.0f;
                        }
                }
            }
            __syncthreads();   // kg1 partials visible to kg0
            if (kg == 0) {
                int tile = cta + (s / 3) * GRID_P;
                int b = tile >> 3, m0 = (tile & 7) << 7;
                float* ob = out + (((size_t)b * COUT) << 10);
                #pragma unroll
                for (int mt = 0; mt < 2; mt++) {
                    int m = wm * 32 + mt * 16 + rl;
                    int gmb = m0 + m;
                    #pragma unroll
                    for (int ntp = 0; ntp < 2; ntp++)
                        #pragma unroll
                        for (int sub = 0; sub < 2; sub++) {
                            int o = wn * 32 + ntp * 16 + sub * 8 + ocl;
                            float* p0 = ob + (((size_t)o) << 10) + 1;
                            float* p1 = ob + (((size_t)(o + 1)) << 10) + 1;
                            float* q = &acc[mt][ntp][sub][0];
                            float v0 = q[0] + stag[o * 128 + m]           + bv[ntp][sub][0];
                            float v1 = q[1] + stag[(o + 1) * 128 + m]     + bv[ntp][sub][1];
                            float v2 = q[2] + stag[o * 128 + m + 8]       + bv[ntp][sub][0];
                            float v3 = q[3] + stag[(o + 1) * 128 + m + 8] + bv[ntp][sub][1];
                            if (gmb < M_) { p0[gmb] = v0; p1[gmb] = v1; }
                            if (gmb + 8 < M_) { p0[gmb + 8] = v2; p1[gmb + 8] = v3; }
                            q[0] = q[1] = q[2] = q[3] = 0.0f;
                        }
                }
            }
        }
    }
}

// ---------------- kernel 4: zero column + optional index tail --------------
__global__ void tail_kernel(const void* __restrict__ idx_raw,
                            float* __restrict__ out, int mode) {
    int i = blockIdx.x * 256 + threadIdx.x;
    const int is64 = g_idx_is64;
    const int* i32 = (const int*)idx_raw;
    const long long* i64 = (const long long*)idx_raw;
    if (i < B_ * COUT) out[(size_t)i * OUTW] = 0.0f;
    if (i < B_ * M3) {
        long long v = is64 ? i64[i] : (long long)i32[i];
        if (mode == 1) {
            out[(size_t)B_ * COUT * OUTW + i] = (float)v;
        } else if (mode == 2) {
            ((long long*)out)[(size_t)(B_ * COUT * OUTW) / 2 + i] = v;
        }
    }
}

// ---------------------------------------------------------------------------
extern "C" void kernel_launch(void* const* d_in, const int* in_sizes, int n_in,
                              void* d_out, int out_size) {
    const float* trees = nullptr;
    const void* indexes = nullptr;
    const float* W = nullptr;
    const float* bias = nullptr;
    for (int i = 0; i < n_in; i++) {
        switch (in_sizes[i]) {
            case B_ * CIN * NPTS: trees   = (const float*)d_in[i]; break;
            case B_ * M3:         indexes = d_in[i];               break;
            case COUT * CIN * 3:  W       = (const float*)d_in[i]; break;
            case COUT:            bias    = (const float*)d_in[i]; break;
        }
    }
    float* out = (float*)d_out;

    cudaFuncSetAttribute(convtree_persist_kernel,
                         cudaFuncAttributeMaxDynamicSharedMemorySize, SMEM_TOTAL);

    detect_kernel<<<1, 256>>>((const int*)indexes);
    transpose_half_kernel<<<dim3(NPTS / 32, CIN / 32, B_), dim3(32, 8)>>>(trees);
    wprep_kernel<<<(3 * 64 * 128 + 255) / 256, 256>>>(W);
    convtree_persist_kernel<<<GRID_P, 512, SMEM_TOTAL>>>(indexes, bias, out);

    long long R = (long long)B_ * COUT * OUTW;
    long long I = (long long)B_ * M3;
    int mode = 0;
    if ((long long)out_size >= R + 2 * I)      mode = 2;
    else if ((long long)out_size >= R + I)     mode = 1;
    tail_kernel<<<(B_ * M3 + 255) / 256, 256>>>(indexes, out, mode);
}

// round 13
// speedup vs baseline: 1.1994x; 1.0113x over previous
#include <cuda_runtime.h>
#include <cuda_fp16.h>
#include <cstdint>

#define B_   256
#define CIN  128
#define NPTS 1024
#define M_   1023
#define COUT 64
#define M3   3069
#define OUTW 1024
#define NTILES 2048          // m-tiles of 128 rows: 8 per batch
#define GRID_P 148
#define NSLOT 4
#define KMAX  14             // ceil(2048/148)

// ---------------- scratch (__device__ globals) ----------------------------
__device__ __half g_th[(size_t)B_ * NPTS * CIN];       // [b][n][c] fp16
__device__ __align__(256) unsigned char g_Wsw[3 * 16384]; // W fp16 image
__device__ int g_idx_is64;

// ---------------- PTX helpers ---------------------------------------------
__device__ __forceinline__ uint32_t smem_u32(const void* p) {
    uint32_t a;
    asm("{ .reg .u64 t; cvta.to.shared.u64 t, %1; cvt.u32.u64 %0, t; }"
        : "=r"(a) : "l"(p));
    return a;
}
#define CP_ASYNC16(dst, src) \
    asm volatile("cp.async.cg.shared.global [%0], [%1], 16;" :: "r"(dst), "l"(src) : "memory")
#define CP_COMMIT() asm volatile("cp.async.commit_group;" ::: "memory")
#define CP_WAIT0()  asm volatile("cp.async.wait_group 0;" ::: "memory")
#define CP_WAIT1()  asm volatile("cp.async.wait_group 1;" ::: "memory")
#define CP_WAIT2()  asm volatile("cp.async.wait_group 2;" ::: "memory")

#define LDSM_X4(r0, r1, r2, r3, addr) \
    asm volatile("ldmatrix.sync.aligned.m8n8.x4.shared.b16 {%0,%1,%2,%3}, [%4];" \
        : "=r"(r0), "=r"(r1), "=r"(r2), "=r"(r3) : "r"(addr))

#define MMA_F16(d, a, b0, b1) \
    asm volatile("mma.sync.aligned.m16n8k16.row.col.f32.f16.f16.f32 " \
        "{%0,%1,%2,%3}, {%4,%5,%6,%7}, {%8,%9}, {%0,%1,%2,%3};" \
        : "+f"((d)[0]), "+f"((d)[1]), "+f"((d)[2]), "+f"((d)[3]) \
        : "r"((a)[0]), "r"((a)[1]), "r"((a)[2]), "r"((a)[3]), "r"(b0), "r"(b1))

// ---------------- kernel 0: index dtype detection --------------------------
__global__ void detect_kernel(const int* __restrict__ idx32) {
    __shared__ int any_nz;
    if (threadIdx.x == 0) any_nz = 0;
    __syncthreads();
    int nz = 0;
    for (int i = threadIdx.x; i < 1024; i += blockDim.x)
        nz |= (idx32[2 * i + 1] != 0);
    if (nz) atomicOr(&any_nz, 1);
    __syncthreads();
    if (threadIdx.x == 0) g_idx_is64 = any_nz ? 0 : 1;
}

// ---------------- kernel 1: transpose + fp16 convert -----------------------
__global__ void transpose_half_kernel(const float* __restrict__ trees) {
    __shared__ float tile[32][33];
    int b = blockIdx.z;
    int nBase = blockIdx.x * 32;
    int cBase = blockIdx.y * 32;
    int tx = threadIdx.x, ty = threadIdx.y;
    const float* src = trees + (size_t)b * CIN * NPTS;
    #pragma unroll
    for (int i = 0; i < 4; i++)
        tile[ty + 8 * i][tx] = src[(size_t)(cBase + ty + 8 * i) * NPTS + nBase + tx];
    __syncthreads();
    #pragma unroll
    for (int i = 0; i < 4; i++) {
        int n = nBase + ty + 8 * i;
        g_th[(size_t)(b * NPTS + n) * CIN + cBase + tx] =
            __float2half(tile[tx][ty + 8 * i]);
    }
}

// ---------------- kernel 2: W -> fp16 swizzled image -----------------------
// byte layout: tap*16384 + o*256 + swz(g,o)*16 + (c&7)*2
__global__ void wprep_kernel(const float* __restrict__ W) {
    int i = blockIdx.x * 256 + threadIdx.x;
    if (i >= 3 * 64 * 128) return;
    int c = i & 127;
    int o = (i >> 7) & 63;
    int k = i >> 13;
    float v = W[(o * CIN + c) * 3 + k];
    int g = c >> 3;
    uint32_t swz = (g & 8) | ((g & 7) ^ (o & 7));
    uint32_t off = k * 16384 + o * 256 + (swz << 4) + (c & 7) * 2;
    *(__half*)(g_Wsw + off) = __float2half(v);
}

// ---------------- kernel 3: persistent gather + HMMA fp16 GEMM -------------
// grid 148, 512 threads: 16 warps = 2 k-groups x (4m x 2n), warp tile 32m x 32o.
// Stage = 128 m-rows of one tap (32KB). 4-slot ring, prefetch distance 3.
// Dedicated 32KB staging buffer for the k-group reduction (no slot reuse).
#define SM_W    0
#define SM_IDX  49152
#define SM_STAG 61440
#define SM_A    94208
#define SMEM_TOTAL (94208 + NSLOT * 32768)   // 225280

__global__ void __launch_bounds__(512, 1) convtree_persist_kernel(
    const void* __restrict__ indexes_raw,
    const float* __restrict__ bias,
    float* __restrict__ out)
{
    extern __shared__ char smem[];
    const uint32_t sb = smem_u32(smem);
    const int tid  = threadIdx.x;
    const int lane = tid & 31;
    const int w    = tid >> 5;
    const int kg   = w >> 3;          // k-group 0/1
    const int wm   = w & 3;           // m-group: rows wm*32 .. wm*32+31
    const int wn   = (w >> 2) & 1;    // n-group: o wn*32 .. wn*32+31
    const int cta  = blockIdx.x;
    const int is64 = g_idx_is64;
    const int* i32 = (const int*)indexes_raw;
    const long long* i64 = (const long long*)indexes_raw;
    uint16_t* sidx = (uint16_t*)(smem + SM_IDX);

    const int K = (NTILES - cta + GRID_P - 1) / GRID_P;
    const int S = 3 * K;

    // ---- W image, loaded once per CTA (pre-swizzled, linear copy) ----
    for (int i = tid; i < 3072; i += 512)
        CP_ASYNC16(sb + SM_W + i * 16, (const char*)g_Wsw + i * 16);
    CP_COMMIT();

    // ---- preload ALL gather indices for this CTA's tiles (uint16) ----
    for (int e = tid; e < K * 384; e += 512) {
        int j = e / 384, i2 = e - j * 384;
        int tile = cta + j * GRID_P;
        int b = tile >> 3, m0 = (tile & 7) << 7;
        int gm = m0 + i2 / 3;
        int v = 0;
        if (gm < M_) {
            int flat = b * M3 + 3 * gm + (i2 % 3);
            v = is64 ? (int)i64[flat] : i32[flat];
        }
        sidx[e] = (uint16_t)(v & (NPTS - 1));
    }

    // ---- per-thread bias values (used by k-group 0 in epilogue) ----
    const int ocl = (lane & 3) * 2;
    float bv[2][2][2];
    #pragma unroll
    for (int ntp = 0; ntp < 2; ntp++)
        #pragma unroll
        for (int sub = 0; sub < 2; sub++) {
            int o = wn * 32 + ntp * 16 + sub * 8 + ocl;
            bv[ntp][sub][0] = bias[o];
            bv[ntp][sub][1] = bias[o + 1];
        }
    __syncthreads();   // sidx visible

    // stage loader: stage s = (local tile s/3, tap s%3) into slot s%NSLOT
    auto load_stage = [&](int s) {
        int j = s / 3, tap = s - 3 * j;
        int tile = cta + j * GRID_P;
        int b = tile >> 3;
        int row = tid >> 2, quarter = tid & 3;
        int n = sidx[j * 384 + row * 3 + tap];
        const char* src = (const char*)(g_th + ((size_t)(b * NPTS + n) << 7))
                          + quarter * 64;
        uint32_t dbase = sb + SM_A + (s % NSLOT) * 32768 + row * 256;
        #pragma unroll
        for (int q = 0; q < 4; q++) {
            int g = quarter * 4 + q;
            uint32_t swz = (g & 8) | ((g & 7) ^ (row & 7));
            CP_ASYNC16(dbase + (swz << 4), src + q * 16);
        }
        CP_COMMIT();
    };

    load_stage(0);
    load_stage(1);
    load_stage(2);

    float acc[2][2][2][4];   // [mt][ntp][sub][quad]
    #pragma unroll
    for (int a = 0; a < 2; a++)
        #pragma unroll
        for (int b2 = 0; b2 < 2; b2++)
            #pragma unroll
            for (int c = 0; c < 2; c++)
                #pragma unroll
                for (int d = 0; d < 4; d++) acc[a][b2][c][d] = 0.0f;

    const int ag = lane >> 4;
    const int bg = (lane >> 3) & 1;
    const int brow_base = wn * 32 + ((lane >> 4) << 3) + (lane & 7);
    const int l7 = lane & 7;
    const int rl = lane >> 2;
    float* stag = (float*)(smem + SM_STAG);   // [o][m] 64x128

    for (int s = 0; s < S; s++) {
        int rem = S - 1 - s;
        if (rem >= 2) CP_WAIT2();
        else if (rem == 1) CP_WAIT1();
        else CP_WAIT0();
        __syncthreads();                     // stage s visible

        if (s + 3 < S) load_stage(s + 3);

        const int tap = s - 3 * (s / 3);
        const uint32_t abase = sb + SM_A + (s % NSLOT) * 32768
                             + (wm * 32 + (lane & 15)) * 256;
        const uint32_t wtap = sb + SM_W + tap * 16384;

        // process k-steps in pairs: burst 8 independent LDSM, then 16 MMA
        #pragma unroll
        for (int kp = 0; kp < 2; kp++) {
            uint32_t af[2][2][4];   // [ks][mt]
            uint32_t bf[2][2][4];   // [ks][ntp]
            #pragma unroll
            for (int ks = 0; ks < 2; ks++) {
                const int g0 = kg * 8 + (kp * 2 + ks) * 2;
                int ga = g0 + ag;
                uint32_t swA = (uint32_t)((ga & 8) | ((ga & 7) ^ l7));
                LDSM_X4(af[ks][0][0], af[ks][0][1], af[ks][0][2], af[ks][0][3],
                        abase + (swA << 4));
                LDSM_X4(af[ks][1][0], af[ks][1][1], af[ks][1][2], af[ks][1][3],
                        abase + 4096 + (swA << 4));
                int gb = g0 + bg;
                uint32_t swB = (uint32_t)((gb & 8) | ((gb & 7) ^ l7));
                LDSM_X4(bf[ks][0][0], bf[ks][0][1], bf[ks][0][2], bf[ks][0][3],
                        wtap + brow_base * 256 + (swB << 4));
                LDSM_X4(bf[ks][1][0], bf[ks][1][1], bf[ks][1][2], bf[ks][1][3],
                        wtap + (brow_base + 16) * 256 + (swB << 4));
            }
            #pragma unroll
            for (int ks = 0; ks < 2; ks++) {
                #pragma unroll
                for (int ntp = 0; ntp < 2; ntp++) {
                    MMA_F16(acc[0][ntp][0], af[ks][0], bf[ks][ntp][0], bf[ks][ntp][1]);
                    MMA_F16(acc[0][ntp][1], af[ks][0], bf[ks][ntp][2], bf[ks][ntp][3]);
                    MMA_F16(acc[1][ntp][0], af[ks][1], bf[ks][ntp][0], bf[ks][ntp][1]);
                    MMA_F16(acc[1][ntp][1], af[ks][1], bf[ks][ntp][2], bf[ks][ntp][3]);
                }
            }
        }

        // ---- after tap 2: kg1 stages partials, kg0 reduces + stores ----
        if (tap == 2) {
            int tile = cta + (s / 3) * GRID_P;
            int b = tile >> 3, m0 = (tile & 7) << 7;
            float* ob = out + (((size_t)b * COUT) << 10);
            if (kg == 1) {
                #pragma unroll
                for (int mt = 0; mt < 2; mt++) {
                    int m = wm * 32 + mt * 16 + rl;
                    #pragma unroll
                    for (int ntp = 0; ntp < 2; ntp++)
                        #pragma unroll
                        for (int sub = 0; sub < 2; sub++) {
                            int o = wn * 32 + ntp * 16 + sub * 8 + ocl;
                            float* q = &acc[mt][ntp][sub][0];
                            stag[o * 128 + m]           = q[0];
                            stag[(o + 1) * 128 + m]     = q[1];
                            stag[o * 128 + m + 8]       = q[2];
                            stag[(o + 1) * 128 + m + 8] = q[3];
                            q[0] = q[1] = q[2] = q[3] = 0.0f;
                        }
                }
                // zero column m=0 (only tiles that own m0 == 0)
                if (m0 == 0 && lane < 8) {
                    int o = (w - 8) * 8 + lane;
                    ob[(size_t)o << 10] = 0.0f;
                }
            }
            __syncthreads();   // kg1 partials visible to kg0
            if (kg == 0) {
                #pragma unroll
                for (int mt = 0; mt < 2; mt++) {
                    int m = wm * 32 + mt * 16 + rl;
                    int gmb = m0 + m;
                    #pragma unroll
                    for (int ntp = 0; ntp < 2; ntp++)
                        #pragma unroll
                        for (int sub = 0; sub < 2; sub++) {
                            int o = wn * 32 + ntp * 16 + sub * 8 + ocl;
                            float* p0 = ob + (((size_t)o) << 10) + 1;
                            float* p1 = ob + (((size_t)(o + 1)) << 10) + 1;
                            float* q = &acc[mt][ntp][sub][0];
                            float v0 = q[0] + stag[o * 128 + m]           + bv[ntp][sub][0];
                            float v1 = q[1] + stag[(o + 1) * 128 + m]     + bv[ntp][sub][1];
                            float v2 = q[2] + stag[o * 128 + m + 8]       + bv[ntp][sub][0];
                            float v3 = q[3] + stag[(o + 1) * 128 + m + 8] + bv[ntp][sub][1];
                            if (gmb < M_) { p0[gmb] = v0; p1[gmb] = v1; }
                            if (gmb + 8 < M_) { p0[gmb + 8] = v2; p1[gmb + 8] = v3; }
                            q[0] = q[1] = q[2] = q[3] = 0.0f;
                        }
                }
            }
        }
    }
}

// ---------------- kernel 4: optional index tail (mode 1/2 only) ------------
__global__ void tail_kernel(const void* __restrict__ idx_raw,
                            float* __restrict__ out, int mode) {
    int i = blockIdx.x * 256 + threadIdx.x;
    const int is64 = g_idx_is64;
    const int* i32 = (const int*)idx_raw;
    const long long* i64 = (const long long*)idx_raw;
    if (i < B_ * M3) {
        long long v = is64 ? i64[i] : (long long)i32[i];
        if (mode == 1) {
            out[(size_t)B_ * COUT * OUTW + i] = (float)v;
        } else if (mode == 2) {
            ((long long*)out)[(size_t)(B_ * COUT * OUTW) / 2 + i] = v;
        }
    }
}

// ---------------------------------------------------------------------------
extern "C" void kernel_launch(void* const* d_in, const int* in_sizes, int n_in,
                              void* d_out, int out_size) {
    const float* trees = nullptr;
    const void* indexes = nullptr;
    const float* W = nullptr;
    const float* bias = nullptr;
    for (int i = 0; i < n_in; i++) {
        switch (in_sizes[i]) {
            case B_ * CIN * NPTS: trees   = (const float*)d_in[i]; break;
            case B_ * M3:         indexes = d_in[i];               break;
            case COUT * CIN * 3:  W       = (const float*)d_in[i]; break;
            case COUT:            bias    = (const float*)d_in[i]; break;
        }
    }
    float* out = (float*)d_out;

    cudaFuncSetAttribute(convtree_persist_kernel,
                         cudaFuncAttributeMaxDynamicSharedMemorySize, SMEM_TOTAL);

    detect_kernel<<<1, 256>>>((const int*)indexes);
    transpose_half_kernel<<<dim3(NPTS / 32, CIN / 32, B_), dim3(32, 8)>>>(trees);
    wprep_kernel<<<(3 * 64 * 128 + 255) / 256, 256>>>(W);
    convtree_persist_kernel<<<GRID_P, 512, SMEM_TOTAL>>>(indexes, bias, out);

    long long R = (long long)B_ * COUT * OUTW;
    long long I = (long long)B_ * M3;
    int mode = 0;
    if ((long long)out_size >= R + 2 * I)      mode = 2;
    else if ((long long)out_size >= R + I)     mode = 1;
    if (mode != 0)
        tail_kernel<<<(B_ * M3 + 255) / 256, 256>>>(indexes, out, mode);
}